// round 1
// baseline (speedup 1.0000x reference)
#include <cuda_runtime.h>
#include <cstdint>

#define FULL_MASK 0xFFFFFFFFu

static constexpr int M = 512;           // factors per token
static constexpr int KSEL = 8;          // top-k
static constexpr int WARPS_PER_BLOCK = 8;
static constexpr int THREADS = WARPS_PER_BLOCK * 32;

// One warp processes one row of 512 floats.
// Each lane owns 16 columns: slot t = 4*j + k  <->  col = j*128 + lane*4 + k.
__global__ void __launch_bounds__(THREADS) qb_gating_kernel(
    const float* __restrict__ logits,
    const float* __restrict__ beta,
    float* __restrict__ out,
    int nrows)
{
    __shared__ float s_beta[M];
    {
        const float4* b4 = reinterpret_cast<const float4*>(beta);
        float4* s4 = reinterpret_cast<float4*>(s_beta);
        for (int i = threadIdx.x; i < M / 4; i += THREADS) s4[i] = b4[i];
    }
    __syncthreads();

    const int lane = threadIdx.x & 31;
    const int warp = threadIdx.x >> 5;
    const int row = blockIdx.x * WARPS_PER_BLOCK + warp;
    if (row >= nrows) return;

    const float4* rp = reinterpret_cast<const float4*>(logits) + (size_t)row * (M / 4);
    const float4* sb4 = reinterpret_cast<const float4*>(s_beta);

    float raw[16];
    float adj[16];
#pragma unroll
    for (int j = 0; j < 4; ++j) {
        float4 v = __ldcs(rp + j * 32 + lane);   // streaming load, no reuse
        float4 b = sb4[j * 32 + lane];
        raw[4 * j + 0] = v.x; adj[4 * j + 0] = v.x - b.x;
        raw[4 * j + 1] = v.y; adj[4 * j + 1] = v.y - b.y;
        raw[4 * j + 2] = v.z; adj[4 * j + 2] = v.z - b.z;
        raw[4 * j + 3] = v.w; adj[4 * j + 3] = v.w - b.w;
    }

    const float NEG_INF = __int_as_float(0xff800000);
    unsigned selmask = 0;          // bit t set -> this lane's slot t was selected
    float topraw[KSEL];            // raw logits of selected factors (all lanes)

#pragma unroll
    for (int it = 0; it < KSEL; ++it) {
        // ---- per-lane argmax over 16 slots ----
        float best = adj[0];
        int bs = 0;
#pragma unroll
        for (int t = 1; t < 16; ++t) {
            if (adj[t] > best) { best = adj[t]; bs = t; }
        }
        int bcol = ((bs >> 2) << 7) | (lane << 2) | (bs & 3);

        // ---- warp argmax, tie-break to lower column (matches jax top_k) ----
#pragma unroll
        for (int off = 16; off > 0; off >>= 1) {
            float ov = __shfl_down_sync(FULL_MASK, best, off);
            int   oc = __shfl_down_sync(FULL_MASK, bcol, off);
            if (ov > best || (ov == best && oc < bcol)) { best = ov; bcol = oc; }
        }
        best = __shfl_sync(FULL_MASK, best, 0);
        bcol = __shfl_sync(FULL_MASK, bcol, 0);

        // raw = adj + beta[col] (reference softmaxes RAW logits at selected cols)
        topraw[it] = best + s_beta[bcol];

        // ---- invalidate winner slot on its owning lane ----
        int wl = (bcol >> 2) & 31;
        int slot = ((bcol >> 7) << 2) | (bcol & 3);
        if (lane == wl) {
            selmask |= 1u << slot;
#pragma unroll
            for (int t = 0; t < 16; ++t)
                if (t == slot) adj[t] = NEG_INF;
        }
    }

    // ---- softmax over the 8 selected raw logits (computed in every lane) ----
    float mv = topraw[0];
#pragma unroll
    for (int i = 1; i < KSEL; ++i) mv = fmaxf(mv, topraw[i]);
    float s = 0.f;
#pragma unroll
    for (int i = 0; i < KSEL; ++i) s += __expf(topraw[i] - mv);
    float inv = __fdividef(1.f, s);

    // ---- scatter: rebuild value per owned column, write full row ----
    float4* op = reinterpret_cast<float4*>(out) + (size_t)row * (M / 4);
#pragma unroll
    for (int j = 0; j < 4; ++j) {
        float4 o;
        float* oc = &o.x;
#pragma unroll
        for (int k = 0; k < 4; ++k) {
            int t = 4 * j + k;
            float e = __expf(raw[t] - mv) * inv;
            oc[k] = ((selmask >> t) & 1u) ? e : 0.f;
        }
        __stcs(op + j * 32 + lane, o);   // streaming store, no reuse
    }
}

extern "C" void kernel_launch(void* const* d_in, const int* in_sizes, int n_in,
                              void* d_out, int out_size) {
    const float* logits = (const float*)d_in[0];
    const float* beta   = (const float*)d_in[1];
    float* out          = (float*)d_out;
    int nrows = in_sizes[0] / M;
    int blocks = (nrows + WARPS_PER_BLOCK - 1) / WARPS_PER_BLOCK;
    qb_gating_kernel<<<blocks, THREADS>>>(logits, beta, out, nrows);
}

// round 2
// speedup vs baseline: 1.6655x; 1.6655x over previous
#include <cuda_runtime.h>
#include <cstdint>

#define FULL_MASK 0xFFFFFFFFu

static constexpr int M = 512;           // factors per token
static constexpr int KSEL = 8;          // top-k
static constexpr int WARPS_PER_BLOCK = 8;
static constexpr int THREADS = WARPS_PER_BLOCK * 32;

// Monotone (order-preserving) float -> uint32 mapping.
__device__ __forceinline__ unsigned f2ord(float f) {
    unsigned u = __float_as_uint(f);
    int s = ((int)u) >> 31;                       // 0 for +, -1 for -
    return u ^ ((unsigned)s | 0x80000000u);       // SHF + LOP3
}

// One warp per row. Lane owns 16 columns: slot t=4j+k <-> col = j*128 + lane*4 + k.
__global__ void __launch_bounds__(THREADS) qb_gating_kernel(
    const float* __restrict__ logits,
    const float* __restrict__ beta,
    float* __restrict__ out,
    int nrows)
{
    __shared__ float s_beta[M];
    {
        const float4* b4 = reinterpret_cast<const float4*>(beta);
        float4* s4 = reinterpret_cast<float4*>(s_beta);
        for (int i = threadIdx.x; i < M / 4; i += THREADS) s4[i] = b4[i];
    }
    __syncthreads();

    const int lane = threadIdx.x & 31;
    const int warp = threadIdx.x >> 5;
    const int row = blockIdx.x * WARPS_PER_BLOCK + warp;
    if (row >= nrows) return;

    const float4* rp = reinterpret_cast<const float4*>(logits) + (size_t)row * (M / 4);
    const float4* sb4 = reinterpret_cast<const float4*>(s_beta);

    float raw[16];
    unsigned key[16];   // orderable keys of debiased logits
#pragma unroll
    for (int j = 0; j < 4; ++j) {
        float4 v = __ldcs(rp + j * 32 + lane);
        float4 b = sb4[j * 32 + lane];
        raw[4 * j + 0] = v.x; key[4 * j + 0] = f2ord(v.x - b.x);
        raw[4 * j + 1] = v.y; key[4 * j + 1] = f2ord(v.y - b.y);
        raw[4 * j + 2] = v.z; key[4 * j + 2] = f2ord(v.z - b.z);
        raw[4 * j + 3] = v.w; key[4 * j + 3] = f2ord(v.w - b.w);
    }

    // ---- per-lane top-3 key VALUES (no index tracking) ----
    unsigned m1, m2, m3;
    {
        unsigned a0 = max(key[0], key[1]),  a1 = max(key[2], key[3]);
        unsigned a2 = max(key[4], key[5]),  a3 = max(key[6], key[7]);
        unsigned a4 = max(key[8], key[9]),  a5 = max(key[10], key[11]);
        unsigned a6 = max(key[12], key[13]),a7 = max(key[14], key[15]);
        m1 = max(max(max(a0, a1), max(a2, a3)), max(max(a4, a5), max(a6, a7)));
    }
    {
        unsigned z[16];
#pragma unroll
        for (int t = 0; t < 16; ++t) z[t] = (key[t] == m1) ? 0u : key[t];
        unsigned a0 = max(z[0], z[1]),  a1 = max(z[2], z[3]);
        unsigned a2 = max(z[4], z[5]),  a3 = max(z[6], z[7]);
        unsigned a4 = max(z[8], z[9]),  a5 = max(z[10], z[11]);
        unsigned a6 = max(z[12], z[13]),a7 = max(z[14], z[15]);
        m2 = max(max(max(a0, a1), max(a2, a3)), max(max(a4, a5), max(a6, a7)));
#pragma unroll
        for (int t = 0; t < 16; ++t) z[t] = (z[t] == m2) ? 0u : z[t];
        a0 = max(z[0], z[1]);   a1 = max(z[2], z[3]);
        a2 = max(z[4], z[5]);   a3 = max(z[6], z[7]);
        a4 = max(z[8], z[9]);   a5 = max(z[10], z[11]);
        a6 = max(z[12], z[13]); a7 = max(z[14], z[15]);
        m3 = max(max(max(a0, a1), max(a2, a3)), max(max(a4, a5), max(a6, a7)));
    }

    // ---- 8 extraction rounds from the 96-candidate pool (32 lanes x 3) ----
    unsigned cur = m1, c1 = m2, c2 = m3;
    int cnt = 0;
    unsigned thr = 0;
#pragma unroll
    for (int it = 0; it < KSEL; ++it) {
        unsigned wmax = __reduce_max_sync(FULL_MASK, cur);
        bool eq = (cur == wmax);
        cur = eq ? c1 : cur;
        c1  = eq ? c2 : c1;
        c2  = eq ? 0u : c2;
        cnt += eq ? 1 : 0;
        thr = wmax;
    }

    unsigned selbits = 0;
    if (__ballot_sync(FULL_MASK, cnt >= 3) == 0u) {
        // FAST: depth-3 lists sufficed -> thr is the exact 8th-largest key.
#pragma unroll
        for (int t = 0; t < 16; ++t)
            selbits |= (key[t] >= thr) ? (1u << t) : 0u;
    } else {
        // SLOW (~4.9% of rows): some lane may hold >=4 of the top-8.
        // Exact 8-round extraction with equality invalidation.
#pragma unroll
        for (int it = 0; it < KSEL; ++it) {
            unsigned a0 = max(key[0], key[1]),  a1 = max(key[2], key[3]);
            unsigned a2 = max(key[4], key[5]),  a3 = max(key[6], key[7]);
            unsigned a4 = max(key[8], key[9]),  a5 = max(key[10], key[11]);
            unsigned a6 = max(key[12], key[13]),a7 = max(key[14], key[15]);
            unsigned lm = max(max(max(a0, a1), max(a2, a3)),
                              max(max(a4, a5), max(a6, a7)));
            unsigned wmax = __reduce_max_sync(FULL_MASK, lm);
            bool eqw = (lm == wmax);
#pragma unroll
            for (int t = 0; t < 16; ++t) {
                bool hit = eqw && (key[t] == wmax);
                selbits |= hit ? (1u << t) : 0u;
                key[t] = hit ? 0u : key[t];
            }
        }
    }

    // ---- softmax over selected RAW logits ----
    const float NEG_INF = __int_as_float(0xff800000);
    float mv = NEG_INF;
#pragma unroll
    for (int t = 0; t < 16; ++t)
        mv = ((selbits >> t) & 1u) ? fmaxf(mv, raw[t]) : mv;
#pragma unroll
    for (int off = 16; off > 0; off >>= 1)
        mv = fmaxf(mv, __shfl_xor_sync(FULL_MASK, mv, off));

    float s = 0.f;
#pragma unroll
    for (int t = 0; t < 16; ++t) {
        float e = __expf(raw[t] - mv);
        s += ((selbits >> t) & 1u) ? e : 0.f;
    }
#pragma unroll
    for (int off = 16; off > 0; off >>= 1)
        s += __shfl_xor_sync(FULL_MASK, s, off);
    float inv = __fdividef(1.f, s);

    // ---- store: recompute exp per group (keeps register count low) ----
    float4* op = reinterpret_cast<float4*>(out) + (size_t)row * (M / 4);
#pragma unroll
    for (int j = 0; j < 4; ++j) {
        float4 o;
        float* oc = &o.x;
#pragma unroll
        for (int k = 0; k < 4; ++k) {
            int t = 4 * j + k;
            float e = __expf(raw[t] - mv) * inv;
            oc[k] = ((selbits >> t) & 1u) ? e : 0.f;
        }
        __stcs(op + j * 32 + lane, o);
    }
}

extern "C" void kernel_launch(void* const* d_in, const int* in_sizes, int n_in,
                              void* d_out, int out_size) {
    const float* logits = (const float*)d_in[0];
    const float* beta   = (const float*)d_in[1];
    float* out          = (float*)d_out;
    int nrows = in_sizes[0] / M;
    int blocks = (nrows + WARPS_PER_BLOCK - 1) / WARPS_PER_BLOCK;
    qb_gating_kernel<<<blocks, THREADS>>>(logits, beta, out, nrows);
}

// round 3
// speedup vs baseline: 1.8782x; 1.1277x over previous
#include <cuda_runtime.h>
#include <cstdint>

#define FULL_MASK 0xFFFFFFFFu

static constexpr int M = 512;           // factors per token
static constexpr int KSEL = 8;          // top-k
static constexpr int WARPS_PER_BLOCK = 8;
static constexpr int THREADS = WARPS_PER_BLOCK * 32;

// Monotone float -> uint32 (order-preserving), and inverse.
__device__ __forceinline__ unsigned f2ord(float f) {
    unsigned u = __float_as_uint(f);
    return u ^ ((unsigned)(((int)u) >> 31) | 0x80000000u);
}
__device__ __forceinline__ float ord2f(unsigned o) {
    unsigned u = o ^ ((o & 0x80000000u) ? 0x80000000u : 0xFFFFFFFFu);
    return __uint_as_float(u);
}

// Pairwise max tree over 16 floats (ILP-friendly).
__device__ __forceinline__ float max16(const float* a) {
    float b0 = fmaxf(a[0], a[1]),   b1 = fmaxf(a[2], a[3]);
    float b2 = fmaxf(a[4], a[5]),   b3 = fmaxf(a[6], a[7]);
    float b4 = fmaxf(a[8], a[9]),   b5 = fmaxf(a[10], a[11]);
    float b6 = fmaxf(a[12], a[13]), b7 = fmaxf(a[14], a[15]);
    return fmaxf(fmaxf(fmaxf(b0, b1), fmaxf(b2, b3)),
                 fmaxf(fmaxf(b4, b5), fmaxf(b6, b7)));
}

// One warp per row. Lane owns 16 columns: slot t=4j+k <-> col = j*128 + lane*4 + k.
__global__ void __launch_bounds__(THREADS) qb_gating_kernel(
    const float* __restrict__ logits,
    const float* __restrict__ beta,
    float* __restrict__ out,
    int nrows)
{
    __shared__ float s_beta[M];
    {
        const float4* b4 = reinterpret_cast<const float4*>(beta);
        float4* s4 = reinterpret_cast<float4*>(s_beta);
        for (int i = threadIdx.x; i < M / 4; i += THREADS) s4[i] = b4[i];
    }
    __syncthreads();

    const int lane = threadIdx.x & 31;
    const int warp = threadIdx.x >> 5;
    const int row = blockIdx.x * WARPS_PER_BLOCK + warp;
    if (row >= nrows) return;

    const float4* rp = reinterpret_cast<const float4*>(logits) + (size_t)row * (M / 4);
    const float4* sb4 = reinterpret_cast<const float4*>(s_beta);

    const float NEG_INF = __int_as_float(0xff800000);

    float raw[16];
    float adj[16];   // debiased logits (selection domain)
#pragma unroll
    for (int j = 0; j < 4; ++j) {
        float4 v = __ldcs(rp + j * 32 + lane);
        float4 b = sb4[j * 32 + lane];
        raw[4 * j + 0] = v.x; adj[4 * j + 0] = v.x - b.x;
        raw[4 * j + 1] = v.y; adj[4 * j + 1] = v.y - b.y;
        raw[4 * j + 2] = v.z; adj[4 * j + 2] = v.z - b.z;
        raw[4 * j + 3] = v.w; adj[4 * j + 3] = v.w - b.w;
    }

    // ---- per-lane top-3 values in float ----
    float m1 = max16(adj);
    float z[16];
#pragma unroll
    for (int t = 0; t < 16; ++t) z[t] = (adj[t] == m1) ? NEG_INF : adj[t];
    float m2 = max16(z);
#pragma unroll
    for (int t = 0; t < 16; ++t) z[t] = (z[t] == m2) ? NEG_INF : z[t];
    float m3 = max16(z);

    // ---- 8 extraction rounds over the 96-candidate pool (int keys for REDUX) ----
    unsigned cur = f2ord(m1), c1 = f2ord(m2), c2 = f2ord(m3);
    unsigned thr = 0;
#pragma unroll
    for (int it = 0; it < KSEL; ++it) {
        unsigned wmax = __reduce_max_sync(FULL_MASK, cur);
        bool eq = (cur == wmax);
        cur = eq ? c1 : cur;
        c1  = eq ? c2 : c1;
        c2  = eq ? 0u : c2;
        thr = wmax;
    }

    // ---- tentative selection by threshold, exact-count validation ----
    float thr_f = ord2f(thr);
    unsigned selbits = 0;
#pragma unroll
    for (int t = 0; t < 16; ++t)
        selbits |= (adj[t] >= thr_f) ? (1u << t) : 0u;
    int n_sel = __reduce_add_sync(FULL_MASK, __popc(selbits));

    if (n_sel != KSEL) {
        // EXACT fallback (~0.2% of rows): index-tracked extraction,
        // tie-break to lower column — bit-matches jax.lax.top_k.
        selbits = 0;
        for (int it = 0; it < KSEL; ++it) {
            float best = adj[0];
            int bs = 0;
#pragma unroll
            for (int t = 1; t < 16; ++t)
                if (adj[t] > best) { best = adj[t]; bs = t; }
            int bcol = ((bs >> 2) << 7) | (lane << 2) | (bs & 3);
#pragma unroll
            for (int off = 16; off > 0; off >>= 1) {
                float ov = __shfl_down_sync(FULL_MASK, best, off);
                int   oc = __shfl_down_sync(FULL_MASK, bcol, off);
                if (ov > best || (ov == best && oc < bcol)) { best = ov; bcol = oc; }
            }
            bcol = __shfl_sync(FULL_MASK, bcol, 0);
            int wl = (bcol >> 2) & 31;
            int slot = ((bcol >> 7) << 2) | (bcol & 3);
            if (lane == wl) {
                selbits |= 1u << slot;
#pragma unroll
                for (int t = 0; t < 16; ++t)
                    if (t == slot) adj[t] = NEG_INF;
            }
        }
    }

    // ---- softmax over selected RAW logits ----
    float mv = NEG_INF;
#pragma unroll
    for (int t = 0; t < 16; ++t)
        mv = ((selbits >> t) & 1u) ? fmaxf(mv, raw[t]) : mv;
#pragma unroll
    for (int off = 16; off > 0; off >>= 1)
        mv = fmaxf(mv, __shfl_xor_sync(FULL_MASK, mv, off));

    // exp once; overwrite raw[] with exp values for the store pass
    float s = 0.f;
#pragma unroll
    for (int t = 0; t < 16; ++t) {
        float e = __expf(raw[t] - mv);
        raw[t] = e;
        s += ((selbits >> t) & 1u) ? e : 0.f;
    }
#pragma unroll
    for (int off = 16; off > 0; off >>= 1)
        s += __shfl_xor_sync(FULL_MASK, s, off);
    float inv = __fdividef(1.f, s);

    // ---- store full row ----
    float4* op = reinterpret_cast<float4*>(out) + (size_t)row * (M / 4);
#pragma unroll
    for (int j = 0; j < 4; ++j) {
        float4 o;
        float* oc = &o.x;
#pragma unroll
        for (int k = 0; k < 4; ++k) {
            int t = 4 * j + k;
            oc[k] = ((selbits >> t) & 1u) ? raw[t] * inv : 0.f;
        }
        __stcs(op + j * 32 + lane, o);
    }
}

extern "C" void kernel_launch(void* const* d_in, const int* in_sizes, int n_in,
                              void* d_out, int out_size) {
    const float* logits = (const float*)d_in[0];
    const float* beta   = (const float*)d_in[1];
    float* out          = (float*)d_out;
    int nrows = in_sizes[0] / M;
    int blocks = (nrows + WARPS_PER_BLOCK - 1) / WARPS_PER_BLOCK;
    qb_gating_kernel<<<blocks, THREADS>>>(logits, beta, out, nrows);
}

// round 4
// speedup vs baseline: 2.1085x; 1.1226x over previous
#include <cuda_runtime.h>
#include <cstdint>

#define FULL_MASK 0xFFFFFFFFu

static constexpr int M = 512;           // factors per token
static constexpr int KSEL = 8;          // top-k
static constexpr int WARPS_PER_BLOCK = 8;
static constexpr int THREADS = WARPS_PER_BLOCK * 32;

// Monotone float -> uint32 (order-preserving), and inverse.
__device__ __forceinline__ unsigned f2ord(float f) {
    unsigned u = __float_as_uint(f);
    return u ^ ((unsigned)(((int)u) >> 31) | 0x80000000u);
}
__device__ __forceinline__ float ord2f(unsigned o) {
    unsigned u = o ^ ((o & 0x80000000u) ? 0x80000000u : 0xFFFFFFFFu);
    return __uint_as_float(u);
}

// One warp per row. Lane owns 16 cols: slot t=4j+k <-> col = j*128 + lane*4 + k.
__global__ void __launch_bounds__(THREADS) qb_gating_kernel(
    const float* __restrict__ logits,
    const float* __restrict__ beta,
    float* __restrict__ out,
    int nrows)
{
    __shared__ float s_beta[M];
    __shared__ float s_ebeta[M];   // exp(beta), for softmax factorization
    for (int i = threadIdx.x; i < M; i += THREADS) {
        float b = beta[i];
        s_beta[i]  = b;
        s_ebeta[i] = __expf(b);
    }
    __syncthreads();

    const int lane = threadIdx.x & 31;
    const int warp = threadIdx.x >> 5;
    const int row = blockIdx.x * WARPS_PER_BLOCK + warp;
    if (row >= nrows) return;

    const float4* rp  = reinterpret_cast<const float4*>(logits) + (size_t)row * (M / 4);
    const float4* sb4 = reinterpret_cast<const float4*>(s_beta);
    const float4* se4 = reinterpret_cast<const float4*>(s_ebeta);

    const float NEG_INF = __int_as_float(0xff800000);

    // ---- load + debias (selection domain only; raw never materialized) ----
    float adj[16];
#pragma unroll
    for (int j = 0; j < 4; ++j) {
        float4 v = __ldcs(rp + j * 32 + lane);
        float4 b = sb4[j * 32 + lane];
        adj[4 * j + 0] = v.x - b.x;
        adj[4 * j + 1] = v.y - b.y;
        adj[4 * j + 2] = v.z - b.z;
        adj[4 * j + 3] = v.w - b.w;
    }

    // ---- per-lane top-3 via sorted-merge tournament (multiset-correct) ----
    float m1, m2, m3;
    {
        // level 0: 8 sorted pairs
        float p1[8], p2[8];
#pragma unroll
        for (int i = 0; i < 8; ++i) {
            p1[i] = fmaxf(adj[2 * i], adj[2 * i + 1]);
            p2[i] = fminf(adj[2 * i], adj[2 * i + 1]);
        }
        // level 1: merge pairs -> 4 sorted triples (top-3 of 4)
        float q1[4], q2[4], q3[4];
#pragma unroll
        for (int i = 0; i < 4; ++i) {
            float a1 = p1[2 * i], a2 = p2[2 * i];
            float b1 = p1[2 * i + 1], b2 = p2[2 * i + 1];
            float c1 = fmaxf(a1, b1), d1 = fminf(a1, b1);
            float c2 = fmaxf(a2, b2), d2 = fminf(a2, b2);
            q1[i] = c1;
            q2[i] = fmaxf(d1, c2);
            q3[i] = fmaxf(fminf(d1, c2), d2);
        }
        // level 2+3: merge sorted triples -> top-3
        float r1[2], r2[2], r3[2];
#pragma unroll
        for (int i = 0; i < 2; ++i) {
            float a1 = q1[2 * i], a2 = q2[2 * i], a3 = q3[2 * i];
            float b1 = q1[2 * i + 1], b2 = q2[2 * i + 1], b3 = q3[2 * i + 1];
            float x = fminf(a1, b1), y = fmaxf(a2, b2);
            r1[i] = fmaxf(a1, b1);
            r2[i] = fmaxf(x, y);
            r3[i] = fmaxf(fminf(x, y), fmaxf(fminf(a2, b2), fmaxf(a3, b3)));
        }
        {
            float a1 = r1[0], a2 = r2[0], a3 = r3[0];
            float b1 = r1[1], b2 = r2[1], b3 = r3[1];
            float x = fminf(a1, b1), y = fmaxf(a2, b2);
            m1 = fmaxf(a1, b1);
            m2 = fmaxf(x, y);
            m3 = fmaxf(fminf(x, y), fmaxf(fminf(a2, b2), fmaxf(a3, b3)));
        }
    }

    // ---- 8 extraction rounds over the 96-candidate pool ----
    unsigned cur = f2ord(m1), c1 = f2ord(m2), c2 = f2ord(m3);
    unsigned thr = 0, c_ord = 0;
#pragma unroll
    for (int it = 0; it < KSEL; ++it) {
        unsigned wmax = __reduce_max_sync(FULL_MASK, cur);
        if (it == 0) c_ord = wmax;     // global max of adj: free softmax stabilizer
        bool eq = (cur == wmax);
        cur = eq ? c1 : cur;
        c1  = eq ? c2 : c1;
        c2  = eq ? 0u : c2;
        thr = wmax;
    }

    // ---- tentative threshold selection + exact-count validation ----
    float thr_f = ord2f(thr);
    unsigned selbits = 0;
#pragma unroll
    for (int t = 0; t < 16; ++t)
        selbits |= (adj[t] >= thr_f) ? (1u << t) : 0u;
    int n_sel = __reduce_add_sync(FULL_MASK, __popc(selbits));

    if (n_sel != KSEL) {
        // EXACT fallback (rare): index-tracked extraction with a used-mask
        // (adj must stay intact for the epilogue). Tie-break to lower column
        // matches jax.lax.top_k.
        unsigned used = 0;
        for (int it = 0; it < KSEL; ++it) {
            float best = NEG_INF;
            int bs = 0;
#pragma unroll
            for (int t = 0; t < 16; ++t) {
                bool ok = !((used >> t) & 1u) && (adj[t] > best);
                best = ok ? adj[t] : best;
                bs = ok ? t : bs;
            }
            int bcol = ((bs >> 2) << 7) | (lane << 2) | (bs & 3);
#pragma unroll
            for (int off = 16; off > 0; off >>= 1) {
                float ov = __shfl_down_sync(FULL_MASK, best, off);
                int   oc = __shfl_down_sync(FULL_MASK, bcol, off);
                if (ov > best || (ov == best && oc < bcol)) { best = ov; bcol = oc; }
            }
            bcol = __shfl_sync(FULL_MASK, bcol, 0);
            if (lane == ((bcol >> 2) & 31))
                used |= 1u << (((bcol >> 7) << 2) | (bcol & 3));
        }
        selbits = used;
    }

    // ---- softmax: exp(raw - c) = exp(adj - c) * exp(beta), c = max adj ----
    float c_f = ord2f(c_ord);
    float s = 0.f;
#pragma unroll
    for (int j = 0; j < 4; ++j) {
        float4 eb = se4[j * 32 + lane];
        const float* ep = &eb.x;
#pragma unroll
        for (int k = 0; k < 4; ++k) {
            int t = 4 * j + k;
            float e = __expf(adj[t] - c_f) * ep[k];
            adj[t] = e;                                   // reuse for store pass
            s += ((selbits >> t) & 1u) ? e : 0.f;
        }
    }
#pragma unroll
    for (int off = 16; off > 0; off >>= 1)
        s += __shfl_xor_sync(FULL_MASK, s, off);
    float inv = __fdividef(1.f, s);

    // ---- store full row ----
    float4* op = reinterpret_cast<float4*>(out) + (size_t)row * (M / 4);
#pragma unroll
    for (int j = 0; j < 4; ++j) {
        float4 o;
        float* oc = &o.x;
#pragma unroll
        for (int k = 0; k < 4; ++k) {
            int t = 4 * j + k;
            oc[k] = ((selbits >> t) & 1u) ? adj[t] * inv : 0.f;
        }
        __stcs(op + j * 32 + lane, o);
    }
}

extern "C" void kernel_launch(void* const* d_in, const int* in_sizes, int n_in,
                              void* d_out, int out_size) {
    const float* logits = (const float*)d_in[0];
    const float* beta   = (const float*)d_in[1];
    float* out          = (float*)d_out;
    int nrows = in_sizes[0] / M;
    int blocks = (nrows + WARPS_PER_BLOCK - 1) / WARPS_PER_BLOCK;
    qb_gating_kernel<<<blocks, THREADS>>>(logits, beta, out, nrows);
}

// round 5
// speedup vs baseline: 2.3705x; 1.1243x over previous
#include <cuda_runtime.h>
#include <cstdint>
#include <cfloat>

#define FULL_MASK 0xFFFFFFFFu

static constexpr int M = 512;           // factors per token
static constexpr int KSEL = 8;          // top-k
static constexpr int WARPS_PER_BLOCK = 8;
static constexpr int THREADS = WARPS_PER_BLOCK * 32;

// Monotone float -> uint32 (order-preserving), and inverse.
__device__ __forceinline__ unsigned f2ord(float f) {
    unsigned u = __float_as_uint(f);
    return u ^ ((unsigned)(((int)u) >> 31) | 0x80000000u);
}
__device__ __forceinline__ float ord2f(unsigned o) {
    unsigned u = o ^ ((o & 0x80000000u) ? 0x80000000u : 0xFFFFFFFFu);
    return __uint_as_float(u);
}
__device__ __forceinline__ float ex2(float x) {
    float r;
    asm("ex2.approx.ftz.f32 %0, %1;" : "=f"(r) : "f"(x));
    return r;
}

// One warp per row. Lane owns 16 cols: slot t=4j+k <-> col = j*128 + lane*4 + k.
// All selection math happens in the log2-scaled domain: adj2 = (logit-beta)*log2e.
__global__ void __launch_bounds__(THREADS) qb_gating_kernel(
    const float* __restrict__ logits,
    const float* __restrict__ beta,
    float* __restrict__ out,
    int nrows)
{
    __shared__ float s_b2[M];      // beta * log2(e)
    __shared__ float s_ebeta[M];   // exp(beta)
    const float LOG2E = 1.4426950408889634f;
    for (int i = threadIdx.x; i < M; i += THREADS) {
        float b = beta[i];
        s_b2[i]    = b * LOG2E;
        s_ebeta[i] = __expf(b);
    }
    __syncthreads();

    const int lane = threadIdx.x & 31;
    const int warp = threadIdx.x >> 5;
    const int row = blockIdx.x * WARPS_PER_BLOCK + warp;
    if (row >= nrows) return;

    const float4* rp  = reinterpret_cast<const float4*>(logits) + (size_t)row * (M / 4);
    const float4* sb4 = reinterpret_cast<const float4*>(s_b2);
    const float4* se4 = reinterpret_cast<const float4*>(s_ebeta);

    const float NEG_INF = __int_as_float(0xff800000);

    // ---- load + debias into exp2 domain: adj2 = v*log2e - beta*log2e ----
    float adj[16];
#pragma unroll
    for (int j = 0; j < 4; ++j) {
        float4 v = __ldcs(rp + j * 32 + lane);
        float4 b = sb4[j * 32 + lane];
        adj[4 * j + 0] = fmaf(v.x, LOG2E, -b.x);
        adj[4 * j + 1] = fmaf(v.y, LOG2E, -b.y);
        adj[4 * j + 2] = fmaf(v.z, LOG2E, -b.z);
        adj[4 * j + 3] = fmaf(v.w, LOG2E, -b.w);
    }

    // ---- per-lane top-3 via sorted-merge tournament (multiset-correct) ----
    float m1, m2, m3;
    {
        float p1[8], p2[8];
#pragma unroll
        for (int i = 0; i < 8; ++i) {
            p1[i] = fmaxf(adj[2 * i], adj[2 * i + 1]);
            p2[i] = fminf(adj[2 * i], adj[2 * i + 1]);
        }
        float q1[4], q2[4], q3[4];
#pragma unroll
        for (int i = 0; i < 4; ++i) {
            float a1 = p1[2 * i], a2 = p2[2 * i];
            float b1 = p1[2 * i + 1], b2 = p2[2 * i + 1];
            float c1 = fmaxf(a1, b1), d1 = fminf(a1, b1);
            float c2 = fmaxf(a2, b2), d2 = fminf(a2, b2);
            q1[i] = c1;
            q2[i] = fmaxf(d1, c2);
            q3[i] = fmaxf(fminf(d1, c2), d2);
        }
        float r1[2], r2[2], r3[2];
#pragma unroll
        for (int i = 0; i < 2; ++i) {
            float a1 = q1[2 * i], a2 = q2[2 * i], a3 = q3[2 * i];
            float b1 = q1[2 * i + 1], b2 = q2[2 * i + 1], b3 = q3[2 * i + 1];
            float x = fminf(a1, b1), y = fmaxf(a2, b2);
            r1[i] = fmaxf(a1, b1);
            r2[i] = fmaxf(x, y);
            r3[i] = fmaxf(fminf(x, y), fmaxf(fminf(a2, b2), fmaxf(a3, b3)));
        }
        {
            float a1 = r1[0], a2 = r2[0], a3 = r3[0];
            float b1 = r1[1], b2 = r2[1], b3 = r3[1];
            float x = fminf(a1, b1), y = fmaxf(a2, b2);
            m1 = fmaxf(a1, b1);
            m2 = fmaxf(x, y);
            m3 = fmaxf(fminf(x, y), fmaxf(fminf(a2, b2), fmaxf(a3, b3)));
        }
    }

    // ---- 8 extraction rounds over the 96-candidate pool ----
    unsigned cur = f2ord(m1), c1 = f2ord(m2), c2 = f2ord(m3);
    unsigned thr = 0, c_ord = 0;
#pragma unroll
    for (int it = 0; it < KSEL; ++it) {
        unsigned wmax = __reduce_max_sync(FULL_MASK, cur);
        if (it == 0) c_ord = wmax;     // global max: free softmax stabilizer
        bool eq = (cur == wmax);
        cur = eq ? c1 : cur;
        c1  = eq ? c2 : c1;
        c2  = eq ? 0u : c2;
        thr = wmax;
    }

    // ---- validate threshold: exactly 8 elements >= thr -> exact top-8 set ----
    float thr_f = ord2f(thr);
    int cnt = 0;
#pragma unroll
    for (int t = 0; t < 16; ++t)
        cnt += (adj[t] >= thr_f) ? 1 : 0;
    int n_sel = __reduce_add_sync(FULL_MASK, cnt);

    if (n_sel != KSEL) {
        // EXACT fallback (rare): index-tracked extraction, lower-column
        // tie-break (bit-matches jax.lax.top_k). Then rewrite adj/thr so the
        // common epilogue selects exactly the chosen slots.
        unsigned used = 0;
        for (int it = 0; it < KSEL; ++it) {
            float best = NEG_INF;
            int bs = 0;
#pragma unroll
            for (int t = 0; t < 16; ++t) {
                bool ok = !((used >> t) & 1u) && (adj[t] > best);
                best = ok ? adj[t] : best;
                bs = ok ? t : bs;
            }
            int bcol = ((bs >> 2) << 7) | (lane << 2) | (bs & 3);
#pragma unroll
            for (int off = 16; off > 0; off >>= 1) {
                float ov = __shfl_down_sync(FULL_MASK, best, off);
                int   oc = __shfl_down_sync(FULL_MASK, bcol, off);
                if (ov > best || (ov == best && oc < bcol)) { best = ov; bcol = oc; }
            }
            bcol = __shfl_sync(FULL_MASK, bcol, 0);
            if (lane == ((bcol >> 2) & 31))
                used |= 1u << (((bcol >> 7) << 2) | (bcol & 3));
        }
#pragma unroll
        for (int t = 0; t < 16; ++t)
            if (!((used >> t) & 1u)) adj[t] = NEG_INF;
        thr_f = -FLT_MAX;
    }

    // ---- masked softmax in one pass: me = sel ? exp2(adj-c)*e^beta : 0 ----
    float c_f = ord2f(c_ord);
    float s = 0.f;
#pragma unroll
    for (int j = 0; j < 4; ++j) {
        float4 eb = se4[j * 32 + lane];
        const float* ep = &eb.x;
#pragma unroll
        for (int k = 0; k < 4; ++k) {
            int t = 4 * j + k;
            bool sel = (adj[t] >= thr_f);
            float e = ex2(adj[t] - c_f) * ep[k];
            float me = sel ? e : 0.f;
            adj[t] = me;
            s += me;
        }
    }
#pragma unroll
    for (int off = 16; off > 0; off >>= 1)
        s += __shfl_xor_sync(FULL_MASK, s, off);
    float inv = __fdividef(1.f, s);

    // ---- store full row ----
    float4* op = reinterpret_cast<float4*>(out) + (size_t)row * (M / 4);
#pragma unroll
    for (int j = 0; j < 4; ++j) {
        float4 o;
        o.x = adj[4 * j + 0] * inv;
        o.y = adj[4 * j + 1] * inv;
        o.z = adj[4 * j + 2] * inv;
        o.w = adj[4 * j + 3] * inv;
        __stcs(op + j * 32 + lane, o);
    }
}

extern "C" void kernel_launch(void* const* d_in, const int* in_sizes, int n_in,
                              void* d_out, int out_size) {
    const float* logits = (const float*)d_in[0];
    const float* beta   = (const float*)d_in[1];
    float* out          = (float*)d_out;
    int nrows = in_sizes[0] / M;
    int blocks = (nrows + WARPS_PER_BLOCK - 1) / WARPS_PER_BLOCK;
    qb_gating_kernel<<<blocks, THREADS>>>(logits, beta, out, nrows);
}